// round 6
// baseline (speedup 1.0000x reference)
#include <cuda_runtime.h>
#include <cuda_bf16.h>
#include <math.h>
#include <stdint.h>

#define NIMG   16
#define NANCH  8732
#define NCLS   80
#define FLATC  (NANCH * NCLS)     // 698560
#define NCAND  400
#define NOUT   200
#define CAP    4096
#define CLIPV  4.135166556742356f // log(1000/16)

// ---------------- device scratch (no allocations allowed) ----------------
__device__ float        g_cls[(size_t)NIMG * NANCH * 81];   // logits
__device__ float        g_scr[(size_t)NIMG * FLATC];        // thresholded softmax scores
__device__ float        g_reg[(size_t)NIMG * NANCH * 4];    // box deltas
__device__ unsigned int g_hist[NIMG * 65536];
__device__ int          g_cnt[NIMG];
__device__ unsigned int g_thr[NIMG];
__device__ float        g_cand_v[NIMG * CAP];
__device__ int          g_cand_i[NIMG * CAP];
__device__ float        g_top_v[NIMG * NCAND];
__device__ int          g_top_i[NIMG * NCAND];

// ---------------- zero histograms ----------------
__global__ void zero_kernel()
{
    int i  = blockIdx.x * blockDim.x + threadIdx.x;
    int st = gridDim.x * blockDim.x;
    for (int t = i; t < NIMG * 65536; t += st) g_hist[t] = 0u;
}

// ---------------- fused cls+reg conv head as implicit GEMM ----------------
// A: rows [0,Mc) = cls_w (m = a*81 + t), rows [Mc,M) = reg_w (m-Mc = a*4 + t)
//    row-major over K = C*9 with k = c*9 + kh*3 + kw  (native weight layout)
// B: implicit im2col, column = img*H*W + oh*W + ow
// Accumulation: FFMA2 into acc_mid; cascaded flush into acc_hi every 24
// k-chunks (24 divides K/8 for every level) -> ~4e-7 rel accumulation noise.
__global__ void __launch_bounds__(256)
head_gemm(const float* __restrict__ feat, const float* __restrict__ cw,
          const float* __restrict__ cb, const float* __restrict__ rw,
          const float* __restrict__ rb,
          int C, int H, int W, int an, int aoff, int Mc, int M, int Ncols)
{
    const int K  = C * 9;
    const int HW = H * W;
    __shared__ __align__(16) float As[8][128];
    __shared__ __align__(16) float Bs[8][128];

    const int tid = threadIdx.x;
    const int m0  = blockIdx.y * 128;
    const int n0  = blockIdx.x * 128;

    // loader mapping: 128 lanes (lm) x 2 k-halves (lk = 0 or 4)
    const int lm = tid & 127;
    const int lk = (tid >> 7) * 4;

    // A row pointer for this loader lane
    const int am = m0 + lm;
    const float* arow = nullptr;
    if (am < Mc)      arow = cw + (size_t)am * K;
    else if (am < M)  arow = rw + (size_t)(am - Mc) * K;

    // B column decode for this loader lane
    const int col = n0 + lm;
    const bool colv = (col < Ncols);
    int img = 0, oh = 0, ow = 0;
    if (colv) { img = col / HW; int r = col % HW; oh = r / W; ow = r % W; }
    const float* fimg = feat + (size_t)img * C * HW;

    const int ty = tid >> 4;   // 0..15 (M dir)
    const int tx = tid & 15;   // 0..15 (N dir)

    // cascaded packed accumulators: mid (FFMA2 target) + hi (flush target)
    unsigned long long accm[8][4], acch[8][4];
#pragma unroll
    for (int i = 0; i < 8; ++i)
#pragma unroll
        for (int u = 0; u < 4; ++u) { accm[i][u] = 0ull; acch[i][u] = 0ull; }

    int fcnt = 0;
    for (int k0 = 0; k0 < K; k0 += 8) {
        // ---- load A tile (float4 per thread, row-major -> As[k][m]) ----
        if (arow) {
            const float4 v = *(const float4*)(arow + k0 + lk);
            As[lk + 0][lm] = v.x; As[lk + 1][lm] = v.y;
            As[lk + 2][lm] = v.z; As[lk + 3][lm] = v.w;
        } else {
            As[lk + 0][lm] = 0.f; As[lk + 1][lm] = 0.f;
            As[lk + 2][lm] = 0.f; As[lk + 3][lm] = 0.f;
        }
        // ---- load B tile (implicit im2col gather) ----
#pragma unroll
        for (int u = 0; u < 4; ++u) {
            const int k = k0 + lk + u;
            float v = 0.f;
            if (colv) {
                const int c  = k / 9;
                const int r  = k - c * 9;
                const int ih = oh + r / 3 - 1;
                const int iw = ow + (r % 3) - 1;
                if ((unsigned)ih < (unsigned)H && (unsigned)iw < (unsigned)W)
                    v = fimg[((size_t)c * H + ih) * W + iw];
            }
            Bs[lk + u][lm] = v;
        }
        __syncthreads();

#pragma unroll
        for (int kk = 0; kk < 8; ++kk) {
            const float4 a0 = *(const float4*)&As[kk][ty * 8];
            const float4 a1 = *(const float4*)&As[kk][ty * 8 + 4];
            const ulonglong2 b0 = *(const ulonglong2*)&Bs[kk][tx * 8];
            const ulonglong2 b1 = *(const ulonglong2*)&Bs[kk][tx * 8 + 4];
            const unsigned long long bp[4] = { b0.x, b0.y, b1.x, b1.y };
            const float av[8] = { a0.x, a0.y, a0.z, a0.w, a1.x, a1.y, a1.z, a1.w };
#pragma unroll
            for (int i = 0; i < 8; ++i) {
                unsigned long long ap;
                asm("mov.b64 %0, {%1, %1};" : "=l"(ap) : "f"(av[i]));
#pragma unroll
                for (int u = 0; u < 4; ++u)
                    asm("fma.rn.f32x2 %0, %1, %2, %0;"
                        : "+l"(accm[i][u]) : "l"(ap), "l"(bp[u]));
            }
        }
        __syncthreads();

        // ---- cascade flush every 24 chunks (K/8 % 24 == 0 for all levels) --
        if (++fcnt == 24) {
            fcnt = 0;
#pragma unroll
            for (int i = 0; i < 8; ++i)
#pragma unroll
                for (int u = 0; u < 4; ++u) {
                    asm("add.rn.f32x2 %0, %0, %1;"
                        : "+l"(acch[i][u]) : "l"(accm[i][u]));
                    accm[i][u] = 0ull;
                }
        }
    }

    // ---- epilogue: bias add + scatter to g_cls / g_reg ----
#pragma unroll
    for (int i = 0; i < 8; ++i) {
        const int m = m0 + ty * 8 + i;
        if (m >= M) continue;
        const float bias = (m < Mc) ? cb[m] : rb[m - Mc];
#pragma unroll
        for (int u = 0; u < 4; ++u) {
            const float lo = __uint_as_float((unsigned)(acch[i][u] & 0xFFFFFFFFull));
            const float hi = __uint_as_float((unsigned)(acch[i][u] >> 32));
#pragma unroll
            for (int half = 0; half < 2; ++half) {
                const int j  = 2 * u + half;
                const int cc = n0 + tx * 8 + j;
                if (cc >= Ncols) continue;
                const float v = (half ? hi : lo) + bias;
                const int im = cc / HW;
                const int r  = cc % HW;
                const int o_h = r / W, o_w = r - o_h * W;
                const int base = (o_h * W + o_w) * an;
                if (m < Mc) {
                    const int a = m / 81, t = m - a * 81;
                    const int anc = aoff + base + a;
                    g_cls[((size_t)im * NANCH + anc) * 81 + t] = v;
                } else {
                    const int mm = m - Mc;
                    const int a = mm >> 2, t = mm & 3;
                    const int anc = aoff + base + a;
                    g_reg[((size_t)im * NANCH + anc) * 4 + t] = v;
                }
            }
        }
    }
}

// ---------------- softmax over 81 classes, drop background, threshold ----
// max reduction is exact; sum reduction done in fp64 and rounded once ->
// removes our reduction-order noise relative to the reference.
__global__ void softmax_kernel()
{
    const int w    = (blockIdx.x * blockDim.x + threadIdx.x) >> 5;
    const int lane = threadIdx.x & 31;
    if (w >= NIMG * NANCH) return;
    const float* in = g_cls + (size_t)w * 81;

    const float NEG = -3.0e38f;
    float v0 = in[lane];
    float v1 = (lane + 32 < 81) ? in[lane + 32] : NEG;
    float v2 = (lane + 64 < 81) ? in[lane + 64] : NEG;
    float m = fmaxf(v0, fmaxf(v1, v2));
#pragma unroll
    for (int off = 16; off > 0; off >>= 1)
        m = fmaxf(m, __shfl_xor_sync(0xFFFFFFFFu, m, off));
    float e0 = expf(v0 - m);
    float e1 = (lane + 32 < 81) ? expf(v1 - m) : 0.f;
    float e2 = (lane + 64 < 81) ? expf(v2 - m) : 0.f;
    double s = (double)e0 + (double)e1 + (double)e2;
#pragma unroll
    for (int off = 16; off > 0; off >>= 1)
        s += __shfl_xor_sync(0xFFFFFFFFu, s, off);
    const float sf = (float)s;

    float* out = g_scr + (size_t)w * NCLS;
    // class c -> scr slot c-1 (background c=0 dropped); threshold at 0.01
    if (lane >= 1) { float p = e0 / sf; out[lane - 1]       = (p > 0.01f) ? p : 0.f; }
    {               float p = e1 / sf; if (lane + 32 < 81) out[lane + 31] = (p > 0.01f) ? p : 0.f; }
    {               float p = e2 / sf; if (lane + 64 < 81) out[lane + 63] = (p > 0.01f) ? p : 0.f; }
}

// ---------------- per-image 16-bit-prefix histogram ----------------
__global__ void hist_kernel()
{
    const int img = blockIdx.y;
    const float* f = g_scr + (size_t)img * FLATC;
    unsigned int* h = g_hist + img * 65536;
    for (int j = blockIdx.x * blockDim.x + threadIdx.x; j < FLATC;
         j += gridDim.x * blockDim.x) {
        const float v = f[j];
        if (v > 0.f) atomicAdd(&h[__float_as_uint(v) >> 16], 1u);
    }
}

// ---------------- find boundary bucket (suffix count >= 400) ----------------
__global__ void boundary_kernel()
{
    __shared__ unsigned int cs[256];
    const int img = blockIdx.x, t = threadIdx.x;
    const unsigned int* h = g_hist + img * 65536;
    unsigned int s = 0;
    const int base = t * 256;
    for (int b = 0; b < 256; ++b) s += h[base + b];
    cs[t] = s;
    __syncthreads();
    if (t == 0) {
        unsigned int acc = 0, thr = 0;
        int chunk = -1;
        for (int c = 255; c >= 0; --c) {
            if (acc + cs[c] >= NCAND) { chunk = c; break; }
            acc += cs[c];
        }
        if (chunk >= 0) {
            for (int b = chunk * 256 + 255; b >= chunk * 256; --b) {
                acc += h[b];
                if (acc >= NCAND) { thr = (unsigned)b; break; }
            }
        }
        g_thr[img] = thr;
        g_cnt[img] = 0;
    }
}

// ---------------- collect top-400 superset ----------------
__global__ void collect_kernel()
{
    const int img = blockIdx.y;
    const unsigned int thr = g_thr[img];
    const float* f = g_scr + (size_t)img * FLATC;
    for (int j = blockIdx.x * blockDim.x + threadIdx.x; j < FLATC;
         j += gridDim.x * blockDim.x) {
        const float v = f[j];
        if (v > 0.f && (__float_as_uint(v) >> 16) >= thr) {
            const int p = atomicAdd(&g_cnt[img], 1);
            if (p < CAP) {
                g_cand_v[img * CAP + p] = v;
                g_cand_i[img * CAP + p] = j;
            }
        }
    }
}

// ---------------- bitonic sort (desc by value, asc by index on ties) ------
__global__ void __launch_bounds__(512) sort_kernel()
{
    __shared__ unsigned long long keys[CAP];
    const int img = blockIdx.x, tid = threadIdx.x;
    int n = g_cnt[img];
    if (n > CAP) n = CAP;

    for (int i = tid; i < CAP; i += 512) {
        unsigned long long key = 0ull;
        if (i < n) {
            const unsigned vb = __float_as_uint(g_cand_v[img * CAP + i]);
            const unsigned ix = (unsigned)g_cand_i[img * CAP + i];
            key = ((unsigned long long)vb << 32) | (0xFFFFFFFFu - ix);
        }
        keys[i] = key;
    }
    __syncthreads();

    for (int k = 2; k <= CAP; k <<= 1) {
        for (int j = k >> 1; j > 0; j >>= 1) {
            for (int i = tid; i < CAP; i += 512) {
                const int ixj = i ^ j;
                if (ixj > i) {
                    const bool desc = ((i & k) == 0);
                    const unsigned long long a = keys[i], b = keys[ixj];
                    if (desc ? (a < b) : (a > b)) { keys[i] = b; keys[ixj] = a; }
                }
            }
            __syncthreads();
        }
    }

    if (tid < NCAND) {
        const unsigned long long key = keys[tid];
        g_top_v[img * NCAND + tid] = __uint_as_float((unsigned)(key >> 32));
        g_top_i[img * NCAND + tid] = (int)(0xFFFFFFFFu - (unsigned)(key & 0xFFFFFFFFull));
    }
    __syncthreads();
    // padding path: fewer than 400 positives -> lax.top_k fills with the
    // lowest-index zero entries
    if (tid == 0 && n < NCAND) {
        const float* f = g_scr + (size_t)img * FLATC;
        int p = n;
        for (int j = 0; j < FLATC && p < NCAND; ++j) {
            if (f[j] == 0.0f) {
                g_top_v[img * NCAND + p] = 0.f;
                g_top_i[img * NCAND + p] = j;
                ++p;
            }
        }
    }
}

// ---------------- decode + class-aware NMS + final top-200 ----------------
__global__ void __launch_bounds__(512)
postnms_kernel(const float* __restrict__ priors, float* __restrict__ out)
{
    __shared__ float sx1[NCAND], sy1[NCAND], sx2[NCAND], sy2[NCAND];
    __shared__ float ox1[NCAND], oy1[NCAND], ox2[NCAND], oy2[NCAND], oar[NCAND];
    __shared__ float s_sc[NCAND];
    __shared__ int   s_cls[NCAND], s_keep[NCAND];
    __shared__ int   s_fi[NOUT];

    const int img = blockIdx.x, tid = threadIdx.x;

    if (tid < NCAND) {
        const float v  = g_top_v[img * NCAND + tid];
        const int idx  = g_top_i[img * NCAND + tid];
        const int cls  = idx % NCLS + 1;
        const int anc  = idx / NCLS;
        const float* d = g_reg + ((size_t)img * NANCH + anc) * 4;
        const float* p = priors + (size_t)anc * 4;
        const float cx = p[0] + d[0] * 0.1f * p[2];
        const float cy = p[1] + d[1] * 0.1f * p[3];
        const float w  = p[2] * expf(fminf(d[2] * 0.2f, CLIPV));
        const float h  = p[3] * expf(fminf(d[3] * 0.2f, CLIPV));
        float x1 = cx - 0.5f * w, y1 = cy - 0.5f * h;
        float x2 = cx + 0.5f * w, y2 = cy + 0.5f * h;
        x1 = fminf(fmaxf(x1, 0.f), 300.f);
        y1 = fminf(fmaxf(y1, 0.f), 300.f);
        x2 = fminf(fmaxf(x2, 0.f), 300.f);
        y2 = fminf(fmaxf(y2, 0.f), 300.f);
        const bool valid = (v > 0.f) && (x2 > x1) && (y2 > y1);
        sx1[tid] = x1; sy1[tid] = y1; sx2[tid] = x2; sy2[tid] = y2;
        s_sc[tid] = valid ? v : 0.f;
        s_cls[tid] = cls;
        s_keep[tid] = valid ? 1 : 0;
        // class offset applied BEFORE area/IoU, exactly as in the reference
        const float off = (float)cls * 301.0f;
        const float a1 = x1 + off, b1 = y1 + off, a2 = x2 + off, b2 = y2 + off;
        ox1[tid] = a1; oy1[tid] = b1; ox2[tid] = a2; oy2[tid] = b2;
        oar[tid] = (a2 - a1) * (b2 - b1);
    }
    __syncthreads();

    // greedy NMS, iteration order identical to the fori_loop
    for (int i = 0; i < NCAND; ++i) {
        if (s_keep[i]) {
            const int j = tid;
            if (j > i && j < NCAND && s_keep[j]) {
                const float ltx = fmaxf(ox1[i], ox1[j]);
                const float lty = fmaxf(oy1[i], oy1[j]);
                const float rbx = fminf(ox2[i], ox2[j]);
                const float rby = fminf(oy2[i], oy2[j]);
                const float ww = fmaxf(rbx - ltx, 0.f);
                const float hh = fmaxf(rby - lty, 0.f);
                const float inter = ww * hh;
                const float iou = inter / (oar[i] + oar[j] - inter + 1e-9f);
                if (iou > 0.45f) s_keep[j] = 0;
            }
        }
        __syncthreads();
    }

    // final top_k(where(keep, s, 0), 200):
    // kept positions ascending (s is already sorted desc), then zero-valued
    // (non-kept) positions ascending -- matches value-desc/index-asc ties.
    if (tid == 0) {
        int p = 0;
        for (int i = 0; i < NCAND && p < NOUT; ++i) if (s_keep[i])  s_fi[p++] = i;
        for (int i = 0; i < NCAND && p < NOUT; ++i) if (!s_keep[i]) s_fi[p++] = i;
    }
    __syncthreads();

    if (tid < NOUT) {
        const int o = s_fi[tid];
        const float fsv = s_keep[o] ? s_sc[o] : 0.f;
        const size_t bo = ((size_t)img * NOUT + tid) * 4;
        out[bo + 0] = sx1[o];
        out[bo + 1] = sy1[o];
        out[bo + 2] = sx2[o];
        out[bo + 3] = sy2[o];
        out[(size_t)NIMG * NOUT * 4 + img * NOUT + tid] = fsv;
        out[(size_t)NIMG * NOUT * 5 + img * NOUT + tid] =
            (fsv > 0.f) ? (float)s_cls[o] : 0.f;
    }
}

// ---------------- host launch ----------------
extern "C" void kernel_launch(void* const* d_in, const int* in_sizes, int n_in,
                              void* d_out, int out_size)
{
    (void)out_size;
    // input-order detection: signature order has feat1 (5,914,624 elems) at
    // slot 1; dict-insertion order has cls_w0 (1,492,992) there.
    const bool sig = (n_in > 1 && in_sizes[1] == 16 * 1024 * 19 * 19);
    int fI[6], cwI[6], cbI[6], rwI[6], rbI[6];
    for (int i = 0; i < 6; ++i) {
        if (sig) {
            fI[i] = i;
            cwI[i] = 6 + 2 * i;  cbI[i] = 7 + 2 * i;
            rwI[i] = 18 + 2 * i; rbI[i] = 19 + 2 * i;
        } else {
            fI[i] = 5 * i;
            cwI[i] = 5 * i + 1; cbI[i] = 5 * i + 2;
            rwI[i] = 5 * i + 3; rbI[i] = 5 * i + 4;
        }
    }
    const float* priors = (const float*)d_in[30];
    float* out = (float*)d_out;

    static const int Cc[6]   = {512, 1024, 512, 256, 256, 256};
    static const int Hh[6]   = {38, 19, 10, 5, 3, 1};
    static const int An[6]   = {4, 6, 6, 6, 4, 4};
    static const int Aoff[6] = {0, 5776, 7942, 8542, 8692, 8728};

    zero_kernel<<<512, 256>>>();

    for (int i = 0; i < 6; ++i) {
        const int H = Hh[i], W = Hh[i], C = Cc[i], an = An[i];
        const int Mc = an * 81, M = an * 85;
        const int Nc = NIMG * H * W;
        dim3 grid((Nc + 127) / 128, (M + 127) / 128);
        head_gemm<<<grid, 256>>>((const float*)d_in[fI[i]],
                                 (const float*)d_in[cwI[i]],
                                 (const float*)d_in[cbI[i]],
                                 (const float*)d_in[rwI[i]],
                                 (const float*)d_in[rbI[i]],
                                 C, H, W, an, Aoff[i], Mc, M, Nc);
    }

    softmax_kernel<<<(NIMG * NANCH + 7) / 8, 256>>>();
    hist_kernel<<<dim3(256, NIMG), 256>>>();
    boundary_kernel<<<NIMG, 256>>>();
    collect_kernel<<<dim3(256, NIMG), 256>>>();
    sort_kernel<<<NIMG, 512>>>();
    postnms_kernel<<<NIMG, 512>>>(priors, out);
}

// round 7
// speedup vs baseline: 1.5134x; 1.5134x over previous
#include <cuda_runtime.h>
#include <cuda_bf16.h>
#include <math.h>
#include <stdint.h>

#define NIMG   16
#define NANCH  8732
#define NCLS   80
#define FLATC  (NANCH * NCLS)     // 698560
#define NCAND  400
#define NOUT   200
#define CAP    4096
#define CLIPV  4.135166556742356f // log(1000/16)

// ---------------- device scratch (no allocations allowed) ----------------
__device__ float        g_cls[(size_t)NIMG * NANCH * 81];   // logits
__device__ float        g_scr[(size_t)NIMG * FLATC];        // thresholded softmax scores
__device__ float        g_reg[(size_t)NIMG * NANCH * 4];    // box deltas
__device__ unsigned int g_hist[NIMG * 65536];
__device__ int          g_cnt[NIMG];
__device__ unsigned int g_thr[NIMG];
__device__ float        g_cand_v[NIMG * CAP];
__device__ int          g_cand_i[NIMG * CAP];
__device__ float        g_top_v[NIMG * NCAND];
__device__ int          g_top_i[NIMG * NCAND];

// ---------------- zero histograms ----------------
__global__ void zero_kernel()
{
    int i  = blockIdx.x * blockDim.x + threadIdx.x;
    int st = gridDim.x * blockDim.x;
    for (int t = i; t < NIMG * 65536; t += st) g_hist[t] = 0u;
}

// ---------------- fused cls+reg conv head as implicit GEMM ----------------
// A: rows [0,Mc) = cls_w (m = a*81 + t), rows [Mc,M) = reg_w (m-Mc = a*4 + t)
//    row-major over K = C*9 with k = c*9 + kh*3 + kw  (native weight layout)
// B: implicit im2col, column = img*H*W + oh*W + ow
// 128x128x16 tile, 256 threads, 8x8 microtile in packed f32x2.
// Double-buffered smem + register prefetch: ONE __syncthreads per k-chunk.
// A is stored duplicated (a,a) so the inner loop is LDS.128 + fma.rn.f32x2
// only. Cascade: accm flushed into acch every 12 chunks (= 192 k-values,
// bitwise identical grouping to the previously passing kernel).
__global__ void __launch_bounds__(256, 1)
head_gemm(const float* __restrict__ feat, const float* __restrict__ cw,
          const float* __restrict__ cb, const float* __restrict__ rw,
          const float* __restrict__ rb,
          int C, int H, int W, int an, int aoff, int Mc, int M, int Ncols)
{
    const int K  = C * 9;            // multiple of 16 for all levels
    const int HW = H * W;
    __shared__ __align__(16) float2 As2[2][16][128];   // duplicated A
    __shared__ __align__(16) float  Bs[2][16][128];

    const int tid = threadIdx.x;
    const int m0  = blockIdx.y * 128;
    const int n0  = blockIdx.x * 128;

    // loader mapping: 128 lanes (lm) x 2 k-halves (lk8 = 0 or 8)
    const int lm  = tid & 127;
    const int lk8 = (tid >> 7) * 8;

    // A row pointer for this loader lane
    const int am = m0 + lm;
    const float* arow = nullptr;
    if (am < Mc)      arow = cw + (size_t)am * K;
    else if (am < M)  arow = rw + (size_t)(am - Mc) * K;

    // B column decode for this loader lane
    const int col = n0 + lm;
    const bool colv = (col < Ncols);
    int img = 0, oh = 0, ow = 0;
    if (colv) { img = col / HW; int r = col % HW; oh = r / W; ow = r % W; }
    const float* fimg = feat + (size_t)img * C * HW;

    const int ty = tid >> 4;   // 0..15 (M dir)
    const int tx = tid & 15;   // 0..15 (N dir)

    // cascaded packed accumulators: mid (FFMA2 target) + hi (flush target)
    unsigned long long accm[8][4], acch[8][4];
#pragma unroll
    for (int i = 0; i < 8; ++i)
#pragma unroll
        for (int u = 0; u < 4; ++u) { accm[i][u] = 0ull; acch[i][u] = 0ull; }

    const int nch = K >> 4;

    // ---- prefetch chunk 0 into registers ----
    float pa[8], pb[8];
    {
#pragma unroll
        for (int u = 0; u < 8; ++u) pa[u] = 0.f;
        if (arow) {
            const float4 v0 = *(const float4*)(arow + lk8);
            const float4 v1 = *(const float4*)(arow + lk8 + 4);
            pa[0] = v0.x; pa[1] = v0.y; pa[2] = v0.z; pa[3] = v0.w;
            pa[4] = v1.x; pa[5] = v1.y; pa[6] = v1.z; pa[7] = v1.w;
        }
#pragma unroll
        for (int u = 0; u < 8; ++u) {
            const int k = lk8 + u;
            float v = 0.f;
            if (colv) {
                const int c  = k / 9;
                const int r  = k - c * 9;
                const int ih = oh + r / 3 - 1;
                const int iw = ow + (r % 3) - 1;
                if ((unsigned)ih < (unsigned)H && (unsigned)iw < (unsigned)W)
                    v = fimg[((size_t)c * H + ih) * W + iw];
            }
            pb[u] = v;
        }
    }

    int fcnt = 0;
    int cur  = 0;
    for (int ch = 0; ch < nch; ++ch) {
        // ---- commit prefetched chunk to smem[cur] ----
#pragma unroll
        for (int u = 0; u < 8; ++u) {
            As2[cur][lk8 + u][lm] = make_float2(pa[u], pa[u]);
            Bs [cur][lk8 + u][lm] = pb[u];
        }
        __syncthreads();

        // ---- issue prefetch of next chunk (overlaps with compute) ----
        if (ch + 1 < nch) {
            const int k0 = (ch + 1) << 4;
            if (arow) {
                const float4 v0 = *(const float4*)(arow + k0 + lk8);
                const float4 v1 = *(const float4*)(arow + k0 + lk8 + 4);
                pa[0] = v0.x; pa[1] = v0.y; pa[2] = v0.z; pa[3] = v0.w;
                pa[4] = v1.x; pa[5] = v1.y; pa[6] = v1.z; pa[7] = v1.w;
            }
#pragma unroll
            for (int u = 0; u < 8; ++u) {
                const int k = k0 + lk8 + u;
                float v = 0.f;
                if (colv) {
                    const int c  = k / 9;
                    const int r  = k - c * 9;
                    const int ih = oh + r / 3 - 1;
                    const int iw = ow + (r % 3) - 1;
                    if ((unsigned)ih < (unsigned)H && (unsigned)iw < (unsigned)W)
                        v = fimg[((size_t)c * H + ih) * W + iw];
                }
                pb[u] = v;
            }
        }

        // ---- compute 16-deep chunk from smem[cur] ----
#pragma unroll
        for (int kk = 0; kk < 16; ++kk) {
            const ulonglong2 a01 = *(const ulonglong2*)&As2[cur][kk][ty * 8];
            const ulonglong2 a23 = *(const ulonglong2*)&As2[cur][kk][ty * 8 + 2];
            const ulonglong2 a45 = *(const ulonglong2*)&As2[cur][kk][ty * 8 + 4];
            const ulonglong2 a67 = *(const ulonglong2*)&As2[cur][kk][ty * 8 + 6];
            const ulonglong2 b0  = *(const ulonglong2*)&Bs[cur][kk][tx * 8];
            const ulonglong2 b1  = *(const ulonglong2*)&Bs[cur][kk][tx * 8 + 4];
            const unsigned long long ap[8] =
                { a01.x, a01.y, a23.x, a23.y, a45.x, a45.y, a67.x, a67.y };
            const unsigned long long bp[4] = { b0.x, b0.y, b1.x, b1.y };
#pragma unroll
            for (int i = 0; i < 8; ++i)
#pragma unroll
                for (int u = 0; u < 4; ++u)
                    asm("fma.rn.f32x2 %0, %1, %2, %0;"
                        : "+l"(accm[i][u]) : "l"(ap[i]), "l"(bp[u]));
        }

        // ---- cascade flush every 12 chunks (192 k-values, as before) ----
        if (++fcnt == 12) {
            fcnt = 0;
#pragma unroll
            for (int i = 0; i < 8; ++i)
#pragma unroll
                for (int u = 0; u < 4; ++u) {
                    asm("add.rn.f32x2 %0, %0, %1;"
                        : "+l"(acch[i][u]) : "l"(accm[i][u]));
                    accm[i][u] = 0ull;
                }
        }
        cur ^= 1;
    }

    // ---- epilogue: bias add + scatter to g_cls / g_reg ----
#pragma unroll
    for (int i = 0; i < 8; ++i) {
        const int m = m0 + ty * 8 + i;
        if (m >= M) continue;
        const float bias = (m < Mc) ? cb[m] : rb[m - Mc];
#pragma unroll
        for (int u = 0; u < 4; ++u) {
            const float lo = __uint_as_float((unsigned)(acch[i][u] & 0xFFFFFFFFull));
            const float hi = __uint_as_float((unsigned)(acch[i][u] >> 32));
#pragma unroll
            for (int half = 0; half < 2; ++half) {
                const int j  = 2 * u + half;
                const int cc = n0 + tx * 8 + j;
                if (cc >= Ncols) continue;
                const float v = (half ? hi : lo) + bias;
                const int im = cc / HW;
                const int r  = cc % HW;
                const int o_h = r / W, o_w = r - o_h * W;
                const int base = (o_h * W + o_w) * an;
                if (m < Mc) {
                    const int a = m / 81, t = m - a * 81;
                    const int anc = aoff + base + a;
                    g_cls[((size_t)im * NANCH + anc) * 81 + t] = v;
                } else {
                    const int mm = m - Mc;
                    const int a = mm >> 2, t = mm & 3;
                    const int anc = aoff + base + a;
                    g_reg[((size_t)im * NANCH + anc) * 4 + t] = v;
                }
            }
        }
    }
}

// ---------------- softmax over 81 classes, drop background, threshold ----
// max reduction is exact; sum reduction done in fp64 and rounded once ->
// removes our reduction-order noise relative to the reference.
__global__ void softmax_kernel()
{
    const int w    = (blockIdx.x * blockDim.x + threadIdx.x) >> 5;
    const int lane = threadIdx.x & 31;
    if (w >= NIMG * NANCH) return;
    const float* in = g_cls + (size_t)w * 81;

    const float NEG = -3.0e38f;
    float v0 = in[lane];
    float v1 = (lane + 32 < 81) ? in[lane + 32] : NEG;
    float v2 = (lane + 64 < 81) ? in[lane + 64] : NEG;
    float m = fmaxf(v0, fmaxf(v1, v2));
#pragma unroll
    for (int off = 16; off > 0; off >>= 1)
        m = fmaxf(m, __shfl_xor_sync(0xFFFFFFFFu, m, off));
    float e0 = expf(v0 - m);
    float e1 = (lane + 32 < 81) ? expf(v1 - m) : 0.f;
    float e2 = (lane + 64 < 81) ? expf(v2 - m) : 0.f;
    double s = (double)e0 + (double)e1 + (double)e2;
#pragma unroll
    for (int off = 16; off > 0; off >>= 1)
        s += __shfl_xor_sync(0xFFFFFFFFu, s, off);
    const float sf = (float)s;

    float* out = g_scr + (size_t)w * NCLS;
    // class c -> scr slot c-1 (background c=0 dropped); threshold at 0.01
    if (lane >= 1) { float p = e0 / sf; out[lane - 1]       = (p > 0.01f) ? p : 0.f; }
    {               float p = e1 / sf; if (lane + 32 < 81) out[lane + 31] = (p > 0.01f) ? p : 0.f; }
    {               float p = e2 / sf; if (lane + 64 < 81) out[lane + 63] = (p > 0.01f) ? p : 0.f; }
}

// ---------------- per-image 16-bit-prefix histogram ----------------
__global__ void hist_kernel()
{
    const int img = blockIdx.y;
    const float* f = g_scr + (size_t)img * FLATC;
    unsigned int* h = g_hist + img * 65536;
    for (int j = blockIdx.x * blockDim.x + threadIdx.x; j < FLATC;
         j += gridDim.x * blockDim.x) {
        const float v = f[j];
        if (v > 0.f) atomicAdd(&h[__float_as_uint(v) >> 16], 1u);
    }
}

// ---------------- find boundary bucket (suffix count >= 400) ----------------
__global__ void boundary_kernel()
{
    __shared__ unsigned int cs[256];
    const int img = blockIdx.x, t = threadIdx.x;
    const unsigned int* h = g_hist + img * 65536;
    unsigned int s = 0;
    const int base = t * 256;
    for (int b = 0; b < 256; ++b) s += h[base + b];
    cs[t] = s;
    __syncthreads();
    if (t == 0) {
        unsigned int acc = 0, thr = 0;
        int chunk = -1;
        for (int c = 255; c >= 0; --c) {
            if (acc + cs[c] >= NCAND) { chunk = c; break; }
            acc += cs[c];
        }
        if (chunk >= 0) {
            for (int b = chunk * 256 + 255; b >= chunk * 256; --b) {
                acc += h[b];
                if (acc >= NCAND) { thr = (unsigned)b; break; }
            }
        }
        g_thr[img] = thr;
        g_cnt[img] = 0;
    }
}

// ---------------- collect top-400 superset ----------------
__global__ void collect_kernel()
{
    const int img = blockIdx.y;
    const unsigned int thr = g_thr[img];
    const float* f = g_scr + (size_t)img * FLATC;
    for (int j = blockIdx.x * blockDim.x + threadIdx.x; j < FLATC;
         j += gridDim.x * blockDim.x) {
        const float v = f[j];
        if (v > 0.f && (__float_as_uint(v) >> 16) >= thr) {
            const int p = atomicAdd(&g_cnt[img], 1);
            if (p < CAP) {
                g_cand_v[img * CAP + p] = v;
                g_cand_i[img * CAP + p] = j;
            }
        }
    }
}

// ---------------- bitonic sort (desc by value, asc by index on ties) ------
__global__ void __launch_bounds__(512) sort_kernel()
{
    __shared__ unsigned long long keys[CAP];
    const int img = blockIdx.x, tid = threadIdx.x;
    int n = g_cnt[img];
    if (n > CAP) n = CAP;

    for (int i = tid; i < CAP; i += 512) {
        unsigned long long key = 0ull;
        if (i < n) {
            const unsigned vb = __float_as_uint(g_cand_v[img * CAP + i]);
            const unsigned ix = (unsigned)g_cand_i[img * CAP + i];
            key = ((unsigned long long)vb << 32) | (0xFFFFFFFFu - ix);
        }
        keys[i] = key;
    }
    __syncthreads();

    for (int k = 2; k <= CAP; k <<= 1) {
        for (int j = k >> 1; j > 0; j >>= 1) {
            for (int i = tid; i < CAP; i += 512) {
                const int ixj = i ^ j;
                if (ixj > i) {
                    const bool desc = ((i & k) == 0);
                    const unsigned long long a = keys[i], b = keys[ixj];
                    if (desc ? (a < b) : (a > b)) { keys[i] = b; keys[ixj] = a; }
                }
            }
            __syncthreads();
        }
    }

    if (tid < NCAND) {
        const unsigned long long key = keys[tid];
        g_top_v[img * NCAND + tid] = __uint_as_float((unsigned)(key >> 32));
        g_top_i[img * NCAND + tid] = (int)(0xFFFFFFFFu - (unsigned)(key & 0xFFFFFFFFull));
    }
    __syncthreads();
    // padding path: fewer than 400 positives -> lax.top_k fills with the
    // lowest-index zero entries
    if (tid == 0 && n < NCAND) {
        const float* f = g_scr + (size_t)img * FLATC;
        int p = n;
        for (int j = 0; j < FLATC && p < NCAND; ++j) {
            if (f[j] == 0.0f) {
                g_top_v[img * NCAND + p] = 0.f;
                g_top_i[img * NCAND + p] = j;
                ++p;
            }
        }
    }
}

// ---------------- decode + class-aware NMS + final top-200 ----------------
__global__ void __launch_bounds__(512)
postnms_kernel(const float* __restrict__ priors, float* __restrict__ out)
{
    __shared__ float sx1[NCAND], sy1[NCAND], sx2[NCAND], sy2[NCAND];
    __shared__ float ox1[NCAND], oy1[NCAND], ox2[NCAND], oy2[NCAND], oar[NCAND];
    __shared__ float s_sc[NCAND];
    __shared__ int   s_cls[NCAND], s_keep[NCAND];
    __shared__ int   s_fi[NOUT];

    const int img = blockIdx.x, tid = threadIdx.x;

    if (tid < NCAND) {
        const float v  = g_top_v[img * NCAND + tid];
        const int idx  = g_top_i[img * NCAND + tid];
        const int cls  = idx % NCLS + 1;
        const int anc  = idx / NCLS;
        const float* d = g_reg + ((size_t)img * NANCH + anc) * 4;
        const float* p = priors + (size_t)anc * 4;
        const float cx = p[0] + d[0] * 0.1f * p[2];
        const float cy = p[1] + d[1] * 0.1f * p[3];
        const float w  = p[2] * expf(fminf(d[2] * 0.2f, CLIPV));
        const float h  = p[3] * expf(fminf(d[3] * 0.2f, CLIPV));
        float x1 = cx - 0.5f * w, y1 = cy - 0.5f * h;
        float x2 = cx + 0.5f * w, y2 = cy + 0.5f * h;
        x1 = fminf(fmaxf(x1, 0.f), 300.f);
        y1 = fminf(fmaxf(y1, 0.f), 300.f);
        x2 = fminf(fmaxf(x2, 0.f), 300.f);
        y2 = fminf(fmaxf(y2, 0.f), 300.f);
        const bool valid = (v > 0.f) && (x2 > x1) && (y2 > y1);
        sx1[tid] = x1; sy1[tid] = y1; sx2[tid] = x2; sy2[tid] = y2;
        s_sc[tid] = valid ? v : 0.f;
        s_cls[tid] = cls;
        s_keep[tid] = valid ? 1 : 0;
        // class offset applied BEFORE area/IoU, exactly as in the reference
        const float off = (float)cls * 301.0f;
        const float a1 = x1 + off, b1 = y1 + off, a2 = x2 + off, b2 = y2 + off;
        ox1[tid] = a1; oy1[tid] = b1; ox2[tid] = a2; oy2[tid] = b2;
        oar[tid] = (a2 - a1) * (b2 - b1);
    }
    __syncthreads();

    // greedy NMS, iteration order identical to the fori_loop
    for (int i = 0; i < NCAND; ++i) {
        if (s_keep[i]) {
            const int j = tid;
            if (j > i && j < NCAND && s_keep[j]) {
                const float ltx = fmaxf(ox1[i], ox1[j]);
                const float lty = fmaxf(oy1[i], oy1[j]);
                const float rbx = fminf(ox2[i], ox2[j]);
                const float rby = fminf(oy2[i], oy2[j]);
                const float ww = fmaxf(rbx - ltx, 0.f);
                const float hh = fmaxf(rby - lty, 0.f);
                const float inter = ww * hh;
                const float iou = inter / (oar[i] + oar[j] - inter + 1e-9f);
                if (iou > 0.45f) s_keep[j] = 0;
            }
        }
        __syncthreads();
    }

    // final top_k(where(keep, s, 0), 200):
    // kept positions ascending (s is already sorted desc), then zero-valued
    // (non-kept) positions ascending -- matches value-desc/index-asc ties.
    if (tid == 0) {
        int p = 0;
        for (int i = 0; i < NCAND && p < NOUT; ++i) if (s_keep[i])  s_fi[p++] = i;
        for (int i = 0; i < NCAND && p < NOUT; ++i) if (!s_keep[i]) s_fi[p++] = i;
    }
    __syncthreads();

    if (tid < NOUT) {
        const int o = s_fi[tid];
        const float fsv = s_keep[o] ? s_sc[o] : 0.f;
        const size_t bo = ((size_t)img * NOUT + tid) * 4;
        out[bo + 0] = sx1[o];
        out[bo + 1] = sy1[o];
        out[bo + 2] = sx2[o];
        out[bo + 3] = sy2[o];
        out[(size_t)NIMG * NOUT * 4 + img * NOUT + tid] = fsv;
        out[(size_t)NIMG * NOUT * 5 + img * NOUT + tid] =
            (fsv > 0.f) ? (float)s_cls[o] : 0.f;
    }
}

// ---------------- host launch ----------------
extern "C" void kernel_launch(void* const* d_in, const int* in_sizes, int n_in,
                              void* d_out, int out_size)
{
    (void)out_size;
    // input-order detection: signature order has feat1 (5,914,624 elems) at
    // slot 1; dict-insertion order has cls_w0 (1,492,992) there.
    const bool sig = (n_in > 1 && in_sizes[1] == 16 * 1024 * 19 * 19);
    int fI[6], cwI[6], cbI[6], rwI[6], rbI[6];
    for (int i = 0; i < 6; ++i) {
        if (sig) {
            fI[i] = i;
            cwI[i] = 6 + 2 * i;  cbI[i] = 7 + 2 * i;
            rwI[i] = 18 + 2 * i; rbI[i] = 19 + 2 * i;
        } else {
            fI[i] = 5 * i;
            cwI[i] = 5 * i + 1; cbI[i] = 5 * i + 2;
            rwI[i] = 5 * i + 3; rbI[i] = 5 * i + 4;
        }
    }
    const float* priors = (const float*)d_in[30];
    float* out = (float*)d_out;

    static const int Cc[6]   = {512, 1024, 512, 256, 256, 256};
    static const int Hh[6]   = {38, 19, 10, 5, 3, 1};
    static const int An[6]   = {4, 6, 6, 6, 4, 4};
    static const int Aoff[6] = {0, 5776, 7942, 8542, 8692, 8728};

    zero_kernel<<<512, 256>>>();

    for (int i = 0; i < 6; ++i) {
        const int H = Hh[i], W = Hh[i], C = Cc[i], an = An[i];
        const int Mc = an * 81, M = an * 85;
        const int Nc = NIMG * H * W;
        dim3 grid((Nc + 127) / 128, (M + 127) / 128);
        head_gemm<<<grid, 256>>>((const float*)d_in[fI[i]],
                                 (const float*)d_in[cwI[i]],
                                 (const float*)d_in[cbI[i]],
                                 (const float*)d_in[rwI[i]],
                                 (const float*)d_in[rbI[i]],
                                 C, H, W, an, Aoff[i], Mc, M, Nc);
    }

    softmax_kernel<<<(NIMG * NANCH + 7) / 8, 256>>>();
    hist_kernel<<<dim3(256, NIMG), 256>>>();
    boundary_kernel<<<NIMG, 256>>>();
    collect_kernel<<<dim3(256, NIMG), 256>>>();
    sort_kernel<<<NIMG, 512>>>();
    postnms_kernel<<<NIMG, 512>>>(priors, out);
}

// round 8
// speedup vs baseline: 2.2219x; 1.4682x over previous
#include <cuda_runtime.h>
#include <cuda_bf16.h>
#include <math.h>
#include <stdint.h>

#define NIMG   16
#define NANCH  8732
#define NCLS   80
#define FLATC  (NANCH * NCLS)     // 698560
#define NCAND  400
#define NOUT   200
#define CAP    4096
#define CLIPV  4.135166556742356f // log(1000/16)

// ---------------- device scratch (no allocations allowed) ----------------
__device__ float        g_cls[(size_t)NIMG * NANCH * 81];   // logits
__device__ float        g_scr[(size_t)NIMG * FLATC];        // thresholded softmax scores
__device__ float        g_reg[(size_t)NIMG * NANCH * 4];    // box deltas
__device__ unsigned int g_hist[NIMG * 65536];
__device__ int          g_cnt[NIMG];
__device__ unsigned int g_thr[NIMG];
__device__ float        g_cand_v[NIMG * CAP];
__device__ int          g_cand_i[NIMG * CAP];
__device__ float        g_top_v[NIMG * NCAND];
__device__ int          g_top_i[NIMG * NCAND];

// ---------------- zero histograms ----------------
__global__ void zero_kernel()
{
    int i  = blockIdx.x * blockDim.x + threadIdx.x;
    int st = gridDim.x * blockDim.x;
    for (int t = i; t < NIMG * 65536; t += st) g_hist[t] = 0u;
}

// ---------------- merged fused cls+reg conv heads: ONE launch -------------
// All six levels in a single 804-CTA grid, biggest-K CTAs first, so the HW
// scheduler fills the chip and kills wave-quantization + serialization.
// Per-CTA computation is bit-identical to the previous passing kernel.
//
// Level order within grid: L1(184), L0(543), L2(52), L3(16), L4(6), L5(3).
struct HeadPtrs {
    const float* feat[6];
    const float* cw[6];
    const float* cb[6];
    const float* rw[6];
    const float* rb[6];
};

// per-level tables indexed by ORIGINAL level id
__device__ __constant__ int d_C[6]    = {512, 1024, 512, 256, 256, 256};
__device__ __constant__ int d_H[6]    = {38, 19, 10, 5, 3, 1};
__device__ __constant__ int d_AN[6]   = {4, 6, 6, 6, 4, 4};
__device__ __constant__ int d_AOFF[6] = {0, 5776, 7942, 8542, 8692, 8728};
__device__ __constant__ int d_NX[6]   = {181, 46, 13, 4, 2, 1};  // ceil(Nc/128)

__global__ void __launch_bounds__(256, 1)
head_gemm_all(const HeadPtrs P)
{
    // ---- block -> (level, tile) mapping; work-heavy levels first ----
    const int b = blockIdx.x;
    int li, rel;
    if      (b < 184) { li = 1; rel = b; }
    else if (b < 727) { li = 0; rel = b - 184; }
    else if (b < 779) { li = 2; rel = b - 727; }
    else if (b < 795) { li = 3; rel = b - 779; }
    else if (b < 801) { li = 4; rel = b - 795; }
    else              { li = 5; rel = b - 801; }

    const int C  = d_C[li];
    const int H  = d_H[li];
    const int W  = H;
    const int an = d_AN[li];
    const int aoff = d_AOFF[li];
    const int nx = d_NX[li];
    const int Mc = an * 81;
    const int M  = an * 85;
    const int HW = H * W;
    const int Ncols = NIMG * HW;
    const int K  = C * 9;            // multiple of 16 for all levels

    const float* __restrict__ feat = P.feat[li];
    const float* __restrict__ cw   = P.cw[li];
    const float* __restrict__ cb   = P.cb[li];
    const float* __restrict__ rw   = P.rw[li];
    const float* __restrict__ rb   = P.rb[li];

    __shared__ __align__(16) float2 As2[2][16][128];   // duplicated A
    __shared__ __align__(16) float  Bs[2][16][128];

    const int tid = threadIdx.x;
    const int m0  = (rel / nx) * 128;
    const int n0  = (rel % nx) * 128;

    // loader mapping: 128 lanes (lm) x 2 k-halves (lk8 = 0 or 8)
    const int lm  = tid & 127;
    const int lk8 = (tid >> 7) * 8;

    // A row pointer for this loader lane
    const int am = m0 + lm;
    const float* arow = nullptr;
    if (am < Mc)      arow = cw + (size_t)am * K;
    else if (am < M)  arow = rw + (size_t)(am - Mc) * K;

    // B column decode for this loader lane
    const int col = n0 + lm;
    const bool colv = (col < Ncols);
    int img = 0, oh = 0, ow = 0;
    if (colv) { img = col / HW; int r = col % HW; oh = r / W; ow = r % W; }
    const float* fimg = feat + (size_t)img * C * HW;

    const int ty = tid >> 4;   // 0..15 (M dir)
    const int tx = tid & 15;   // 0..15 (N dir)

    // cascaded packed accumulators: mid (FFMA2 target) + hi (flush target)
    unsigned long long accm[8][4], acch[8][4];
#pragma unroll
    for (int i = 0; i < 8; ++i)
#pragma unroll
        for (int u = 0; u < 4; ++u) { accm[i][u] = 0ull; acch[i][u] = 0ull; }

    const int nch = K >> 4;

    // ---- prefetch chunk 0 into registers ----
    float pa[8], pb[8];
    {
#pragma unroll
        for (int u = 0; u < 8; ++u) pa[u] = 0.f;
        if (arow) {
            const float4 v0 = *(const float4*)(arow + lk8);
            const float4 v1 = *(const float4*)(arow + lk8 + 4);
            pa[0] = v0.x; pa[1] = v0.y; pa[2] = v0.z; pa[3] = v0.w;
            pa[4] = v1.x; pa[5] = v1.y; pa[6] = v1.z; pa[7] = v1.w;
        }
#pragma unroll
        for (int u = 0; u < 8; ++u) {
            const int k = lk8 + u;
            float v = 0.f;
            if (colv) {
                const int c  = k / 9;
                const int r  = k - c * 9;
                const int ih = oh + r / 3 - 1;
                const int iw = ow + (r % 3) - 1;
                if ((unsigned)ih < (unsigned)H && (unsigned)iw < (unsigned)W)
                    v = fimg[((size_t)c * H + ih) * W + iw];
            }
            pb[u] = v;
        }
    }

    int fcnt = 0;
    int cur  = 0;
    for (int ch = 0; ch < nch; ++ch) {
        // ---- commit prefetched chunk to smem[cur] ----
#pragma unroll
        for (int u = 0; u < 8; ++u) {
            As2[cur][lk8 + u][lm] = make_float2(pa[u], pa[u]);
            Bs [cur][lk8 + u][lm] = pb[u];
        }
        __syncthreads();

        // ---- issue prefetch of next chunk (overlaps with compute) ----
        if (ch + 1 < nch) {
            const int k0 = (ch + 1) << 4;
            if (arow) {
                const float4 v0 = *(const float4*)(arow + k0 + lk8);
                const float4 v1 = *(const float4*)(arow + k0 + lk8 + 4);
                pa[0] = v0.x; pa[1] = v0.y; pa[2] = v0.z; pa[3] = v0.w;
                pa[4] = v1.x; pa[5] = v1.y; pa[6] = v1.z; pa[7] = v1.w;
            }
#pragma unroll
            for (int u = 0; u < 8; ++u) {
                const int k = k0 + lk8 + u;
                float v = 0.f;
                if (colv) {
                    const int c  = k / 9;
                    const int r  = k - c * 9;
                    const int ih = oh + r / 3 - 1;
                    const int iw = ow + (r % 3) - 1;
                    if ((unsigned)ih < (unsigned)H && (unsigned)iw < (unsigned)W)
                        v = fimg[((size_t)c * H + ih) * W + iw];
                }
                pb[u] = v;
            }
        }

        // ---- compute 16-deep chunk from smem[cur] ----
#pragma unroll
        for (int kk = 0; kk < 16; ++kk) {
            const ulonglong2 a01 = *(const ulonglong2*)&As2[cur][kk][ty * 8];
            const ulonglong2 a23 = *(const ulonglong2*)&As2[cur][kk][ty * 8 + 2];
            const ulonglong2 a45 = *(const ulonglong2*)&As2[cur][kk][ty * 8 + 4];
            const ulonglong2 a67 = *(const ulonglong2*)&As2[cur][kk][ty * 8 + 6];
            const ulonglong2 b0  = *(const ulonglong2*)&Bs[cur][kk][tx * 8];
            const ulonglong2 b1  = *(const ulonglong2*)&Bs[cur][kk][tx * 8 + 4];
            const unsigned long long ap[8] =
                { a01.x, a01.y, a23.x, a23.y, a45.x, a45.y, a67.x, a67.y };
            const unsigned long long bp[4] = { b0.x, b0.y, b1.x, b1.y };
#pragma unroll
            for (int i = 0; i < 8; ++i)
#pragma unroll
                for (int u = 0; u < 4; ++u)
                    asm("fma.rn.f32x2 %0, %1, %2, %0;"
                        : "+l"(accm[i][u]) : "l"(ap[i]), "l"(bp[u]));
        }

        // ---- cascade flush every 12 chunks (192 k-values, as before) ----
        if (++fcnt == 12) {
            fcnt = 0;
#pragma unroll
            for (int i = 0; i < 8; ++i)
#pragma unroll
                for (int u = 0; u < 4; ++u) {
                    asm("add.rn.f32x2 %0, %0, %1;"
                        : "+l"(acch[i][u]) : "l"(accm[i][u]));
                    accm[i][u] = 0ull;
                }
        }
        cur ^= 1;
    }

    // ---- epilogue: bias add + scatter to g_cls / g_reg ----
#pragma unroll
    for (int i = 0; i < 8; ++i) {
        const int m = m0 + ty * 8 + i;
        if (m >= M) continue;
        const float bias = (m < Mc) ? cb[m] : rb[m - Mc];
#pragma unroll
        for (int u = 0; u < 4; ++u) {
            const float lo = __uint_as_float((unsigned)(acch[i][u] & 0xFFFFFFFFull));
            const float hi = __uint_as_float((unsigned)(acch[i][u] >> 32));
#pragma unroll
            for (int half = 0; half < 2; ++half) {
                const int j  = 2 * u + half;
                const int cc = n0 + tx * 8 + j;
                if (cc >= Ncols) continue;
                const float v = (half ? hi : lo) + bias;
                const int im = cc / HW;
                const int r  = cc % HW;
                const int o_h = r / W, o_w = r - o_h * W;
                const int base = (o_h * W + o_w) * an;
                if (m < Mc) {
                    const int a = m / 81, t = m - a * 81;
                    const int anc = aoff + base + a;
                    g_cls[((size_t)im * NANCH + anc) * 81 + t] = v;
                } else {
                    const int mm = m - Mc;
                    const int a = mm >> 2, t = mm & 3;
                    const int anc = aoff + base + a;
                    g_reg[((size_t)im * NANCH + anc) * 4 + t] = v;
                }
            }
        }
    }
}

// ---------------- softmax over 81 classes, drop background, threshold ----
// max reduction is exact; sum reduction done in fp64 and rounded once ->
// removes our reduction-order noise relative to the reference.
__global__ void softmax_kernel()
{
    const int w    = (blockIdx.x * blockDim.x + threadIdx.x) >> 5;
    const int lane = threadIdx.x & 31;
    if (w >= NIMG * NANCH) return;
    const float* in = g_cls + (size_t)w * 81;

    const float NEG = -3.0e38f;
    float v0 = in[lane];
    float v1 = (lane + 32 < 81) ? in[lane + 32] : NEG;
    float v2 = (lane + 64 < 81) ? in[lane + 64] : NEG;
    float m = fmaxf(v0, fmaxf(v1, v2));
#pragma unroll
    for (int off = 16; off > 0; off >>= 1)
        m = fmaxf(m, __shfl_xor_sync(0xFFFFFFFFu, m, off));
    float e0 = expf(v0 - m);
    float e1 = (lane + 32 < 81) ? expf(v1 - m) : 0.f;
    float e2 = (lane + 64 < 81) ? expf(v2 - m) : 0.f;
    double s = (double)e0 + (double)e1 + (double)e2;
#pragma unroll
    for (int off = 16; off > 0; off >>= 1)
        s += __shfl_xor_sync(0xFFFFFFFFu, s, off);
    const float sf = (float)s;

    float* out = g_scr + (size_t)w * NCLS;
    // class c -> scr slot c-1 (background c=0 dropped); threshold at 0.01
    if (lane >= 1) { float p = e0 / sf; out[lane - 1]       = (p > 0.01f) ? p : 0.f; }
    {               float p = e1 / sf; if (lane + 32 < 81) out[lane + 31] = (p > 0.01f) ? p : 0.f; }
    {               float p = e2 / sf; if (lane + 64 < 81) out[lane + 63] = (p > 0.01f) ? p : 0.f; }
}

// ---------------- per-image 16-bit-prefix histogram ----------------
__global__ void hist_kernel()
{
    const int img = blockIdx.y;
    const float* f = g_scr + (size_t)img * FLATC;
    unsigned int* h = g_hist + img * 65536;
    for (int j = blockIdx.x * blockDim.x + threadIdx.x; j < FLATC;
         j += gridDim.x * blockDim.x) {
        const float v = f[j];
        if (v > 0.f) atomicAdd(&h[__float_as_uint(v) >> 16], 1u);
    }
}

// ---------------- find boundary bucket (suffix count >= 400) ----------------
__global__ void boundary_kernel()
{
    __shared__ unsigned int cs[256];
    const int img = blockIdx.x, t = threadIdx.x;
    const unsigned int* h = g_hist + img * 65536;
    unsigned int s = 0;
    const int base = t * 256;
    for (int b = 0; b < 256; ++b) s += h[base + b];
    cs[t] = s;
    __syncthreads();
    if (t == 0) {
        unsigned int acc = 0, thr = 0;
        int chunk = -1;
        for (int c = 255; c >= 0; --c) {
            if (acc + cs[c] >= NCAND) { chunk = c; break; }
            acc += cs[c];
        }
        if (chunk >= 0) {
            for (int b = chunk * 256 + 255; b >= chunk * 256; --b) {
                acc += h[b];
                if (acc >= NCAND) { thr = (unsigned)b; break; }
            }
        }
        g_thr[img] = thr;
        g_cnt[img] = 0;
    }
}

// ---------------- collect top-400 superset ----------------
__global__ void collect_kernel()
{
    const int img = blockIdx.y;
    const unsigned int thr = g_thr[img];
    const float* f = g_scr + (size_t)img * FLATC;
    for (int j = blockIdx.x * blockDim.x + threadIdx.x; j < FLATC;
         j += gridDim.x * blockDim.x) {
        const float v = f[j];
        if (v > 0.f && (__float_as_uint(v) >> 16) >= thr) {
            const int p = atomicAdd(&g_cnt[img], 1);
            if (p < CAP) {
                g_cand_v[img * CAP + p] = v;
                g_cand_i[img * CAP + p] = j;
            }
        }
    }
}

// ---------------- bitonic sort (desc by value, asc by index on ties) ------
__global__ void __launch_bounds__(512) sort_kernel()
{
    __shared__ unsigned long long keys[CAP];
    const int img = blockIdx.x, tid = threadIdx.x;
    int n = g_cnt[img];
    if (n > CAP) n = CAP;

    for (int i = tid; i < CAP; i += 512) {
        unsigned long long key = 0ull;
        if (i < n) {
            const unsigned vb = __float_as_uint(g_cand_v[img * CAP + i]);
            const unsigned ix = (unsigned)g_cand_i[img * CAP + i];
            key = ((unsigned long long)vb << 32) | (0xFFFFFFFFu - ix);
        }
        keys[i] = key;
    }
    __syncthreads();

    for (int k = 2; k <= CAP; k <<= 1) {
        for (int j = k >> 1; j > 0; j >>= 1) {
            for (int i = tid; i < CAP; i += 512) {
                const int ixj = i ^ j;
                if (ixj > i) {
                    const bool desc = ((i & k) == 0);
                    const unsigned long long a = keys[i], b = keys[ixj];
                    if (desc ? (a < b) : (a > b)) { keys[i] = b; keys[ixj] = a; }
                }
            }
            __syncthreads();
        }
    }

    if (tid < NCAND) {
        const unsigned long long key = keys[tid];
        g_top_v[img * NCAND + tid] = __uint_as_float((unsigned)(key >> 32));
        g_top_i[img * NCAND + tid] = (int)(0xFFFFFFFFu - (unsigned)(key & 0xFFFFFFFFull));
    }
    __syncthreads();
    // padding path: fewer than 400 positives -> lax.top_k fills with the
    // lowest-index zero entries
    if (tid == 0 && n < NCAND) {
        const float* f = g_scr + (size_t)img * FLATC;
        int p = n;
        for (int j = 0; j < FLATC && p < NCAND; ++j) {
            if (f[j] == 0.0f) {
                g_top_v[img * NCAND + p] = 0.f;
                g_top_i[img * NCAND + p] = j;
                ++p;
            }
        }
    }
}

// ---------------- decode + class-aware NMS + final top-200 ----------------
__global__ void __launch_bounds__(512)
postnms_kernel(const float* __restrict__ priors, float* __restrict__ out)
{
    __shared__ float sx1[NCAND], sy1[NCAND], sx2[NCAND], sy2[NCAND];
    __shared__ float ox1[NCAND], oy1[NCAND], ox2[NCAND], oy2[NCAND], oar[NCAND];
    __shared__ float s_sc[NCAND];
    __shared__ int   s_cls[NCAND], s_keep[NCAND];
    __shared__ int   s_fi[NOUT];

    const int img = blockIdx.x, tid = threadIdx.x;

    if (tid < NCAND) {
        const float v  = g_top_v[img * NCAND + tid];
        const int idx  = g_top_i[img * NCAND + tid];
        const int cls  = idx % NCLS + 1;
        const int anc  = idx / NCLS;
        const float* d = g_reg + ((size_t)img * NANCH + anc) * 4;
        const float* p = priors + (size_t)anc * 4;
        const float cx = p[0] + d[0] * 0.1f * p[2];
        const float cy = p[1] + d[1] * 0.1f * p[3];
        const float w  = p[2] * expf(fminf(d[2] * 0.2f, CLIPV));
        const float h  = p[3] * expf(fminf(d[3] * 0.2f, CLIPV));
        float x1 = cx - 0.5f * w, y1 = cy - 0.5f * h;
        float x2 = cx + 0.5f * w, y2 = cy + 0.5f * h;
        x1 = fminf(fmaxf(x1, 0.f), 300.f);
        y1 = fminf(fmaxf(y1, 0.f), 300.f);
        x2 = fminf(fmaxf(x2, 0.f), 300.f);
        y2 = fminf(fmaxf(y2, 0.f), 300.f);
        const bool valid = (v > 0.f) && (x2 > x1) && (y2 > y1);
        sx1[tid] = x1; sy1[tid] = y1; sx2[tid] = x2; sy2[tid] = y2;
        s_sc[tid] = valid ? v : 0.f;
        s_cls[tid] = cls;
        s_keep[tid] = valid ? 1 : 0;
        // class offset applied BEFORE area/IoU, exactly as in the reference
        const float off = (float)cls * 301.0f;
        const float a1 = x1 + off, b1 = y1 + off, a2 = x2 + off, b2 = y2 + off;
        ox1[tid] = a1; oy1[tid] = b1; ox2[tid] = a2; oy2[tid] = b2;
        oar[tid] = (a2 - a1) * (b2 - b1);
    }
    __syncthreads();

    // greedy NMS, iteration order identical to the fori_loop
    for (int i = 0; i < NCAND; ++i) {
        if (s_keep[i]) {
            const int j = tid;
            if (j > i && j < NCAND && s_keep[j]) {
                const float ltx = fmaxf(ox1[i], ox1[j]);
                const float lty = fmaxf(oy1[i], oy1[j]);
                const float rbx = fminf(ox2[i], ox2[j]);
                const float rby = fminf(oy2[i], oy2[j]);
                const float ww = fmaxf(rbx - ltx, 0.f);
                const float hh = fmaxf(rby - lty, 0.f);
                const float inter = ww * hh;
                const float iou = inter / (oar[i] + oar[j] - inter + 1e-9f);
                if (iou > 0.45f) s_keep[j] = 0;
            }
        }
        __syncthreads();
    }

    // final top_k(where(keep, s, 0), 200):
    // kept positions ascending (s is already sorted desc), then zero-valued
    // (non-kept) positions ascending -- matches value-desc/index-asc ties.
    if (tid == 0) {
        int p = 0;
        for (int i = 0; i < NCAND && p < NOUT; ++i) if (s_keep[i])  s_fi[p++] = i;
        for (int i = 0; i < NCAND && p < NOUT; ++i) if (!s_keep[i]) s_fi[p++] = i;
    }
    __syncthreads();

    if (tid < NOUT) {
        const int o = s_fi[tid];
        const float fsv = s_keep[o] ? s_sc[o] : 0.f;
        const size_t bo = ((size_t)img * NOUT + tid) * 4;
        out[bo + 0] = sx1[o];
        out[bo + 1] = sy1[o];
        out[bo + 2] = sx2[o];
        out[bo + 3] = sy2[o];
        out[(size_t)NIMG * NOUT * 4 + img * NOUT + tid] = fsv;
        out[(size_t)NIMG * NOUT * 5 + img * NOUT + tid] =
            (fsv > 0.f) ? (float)s_cls[o] : 0.f;
    }
}

// ---------------- host launch ----------------
extern "C" void kernel_launch(void* const* d_in, const int* in_sizes, int n_in,
                              void* d_out, int out_size)
{
    (void)out_size;
    // input-order detection: signature order has feat1 (5,914,624 elems) at
    // slot 1; dict-insertion order has cls_w0 (1,492,992) there.
    const bool sig = (n_in > 1 && in_sizes[1] == 16 * 1024 * 19 * 19);
    int fI[6], cwI[6], cbI[6], rwI[6], rbI[6];
    for (int i = 0; i < 6; ++i) {
        if (sig) {
            fI[i] = i;
            cwI[i] = 6 + 2 * i;  cbI[i] = 7 + 2 * i;
            rwI[i] = 18 + 2 * i; rbI[i] = 19 + 2 * i;
        } else {
            fI[i] = 5 * i;
            cwI[i] = 5 * i + 1; cbI[i] = 5 * i + 2;
            rwI[i] = 5 * i + 3; rbI[i] = 5 * i + 4;
        }
    }
    const float* priors = (const float*)d_in[30];
    float* out = (float*)d_out;

    HeadPtrs P;
    for (int i = 0; i < 6; ++i) {
        P.feat[i] = (const float*)d_in[fI[i]];
        P.cw[i]   = (const float*)d_in[cwI[i]];
        P.cb[i]   = (const float*)d_in[cbI[i]];
        P.rw[i]   = (const float*)d_in[rwI[i]];
        P.rb[i]   = (const float*)d_in[rbI[i]];
    }

    zero_kernel<<<512, 256>>>();

    // single merged launch: 184(L1) + 543(L0) + 52(L2) + 16(L3) + 6(L4) + 3(L5)
    head_gemm_all<<<804, 256>>>(P);

    softmax_kernel<<<(NIMG * NANCH + 7) / 8, 256>>>();
    hist_kernel<<<dim3(256, NIMG), 256>>>();
    boundary_kernel<<<NIMG, 256>>>();
    collect_kernel<<<dim3(256, NIMG), 256>>>();
    sort_kernel<<<NIMG, 512>>>();
    postnms_kernel<<<NIMG, 512>>>(priors, out);
}